// round 1
// baseline (speedup 1.0000x reference)
#include <cuda_runtime.h>
#include <cuda_bf16.h>
#include <cstdint>

// Problem constants (fixed shapes)
#define B_SZ   256
#define T_SZ   512
#define EMB    128
#define HID    256
#define NCLS   32000

// Scratch: h0 at last timestep, stored bf16 for tensor-core GEMM
__device__ __nv_bfloat16 g_h0[B_SZ * HID];

// ---------------------------------------------------------------------------
// Kernel 1: h0_last[b, h] for the 256 last-timestep tokens.
//   i0 = sigmoid(E@U_i + b_i); g0 = tanh(E@U_c + b_c); o0 = sigmoid(E@U_o + b_o)
//   h0 = o0 * tanh(i0 * g0)
// Grid: 64 blocks x 256 threads; each block handles 4 batch rows (amortizes
// U-matrix L2 traffic), each thread owns one hidden unit h.
// ---------------------------------------------------------------------------
__global__ void __launch_bounds__(256) lstm_h0_kernel(
    const int* __restrict__ X, const float* __restrict__ C_table,
    const float* __restrict__ U_i, const float* __restrict__ b_i,
    const float* __restrict__ U_c, const float* __restrict__ b_c,
    const float* __restrict__ U_o, const float* __restrict__ b_o)
{
    __shared__ float E_s[4][EMB];
    const int b0 = blockIdx.x * 4;
    const int tid = threadIdx.x;

    // Gather last-timestep embeddings for the 4 batch rows of this block
    for (int i = tid; i < 4 * EMB; i += 256) {
        int b = i >> 7;          // /128
        int e = i & (EMB - 1);
        int tok = X[(b0 + b) * T_SZ + (T_SZ - 1)];
        E_s[b][e] = C_table[tok * EMB + e];
    }
    __syncthreads();

    const int h = tid;
    float ai[4], ag[4], ao[4];
    const float bi = b_i[h], bc = b_c[h], bo = b_o[h];
#pragma unroll
    for (int b = 0; b < 4; b++) { ai[b] = bi; ag[b] = bc; ao[b] = bo; }

#pragma unroll 4
    for (int e = 0; e < EMB; e++) {
        float ui = U_i[e * HID + h];
        float uc = U_c[e * HID + h];
        float uo = U_o[e * HID + h];
#pragma unroll
        for (int b = 0; b < 4; b++) {
            float ev = E_s[b][e];
            ai[b] = fmaf(ev, ui, ai[b]);
            ag[b] = fmaf(ev, uc, ag[b]);
            ao[b] = fmaf(ev, uo, ao[b]);
        }
    }

#pragma unroll
    for (int b = 0; b < 4; b++) {
        float i0 = 1.0f / (1.0f + __expf(-ai[b]));
        float g0 = tanhf(ag[b]);
        float o0 = 1.0f / (1.0f + __expf(-ao[b]));
        float c0 = i0 * g0;
        float h0 = o0 * tanhf(c0);
        g_h0[(b0 + b) * HID + h] = __float2bfloat16(h0);
    }
}

// ---------------------------------------------------------------------------
// Kernel 2: logits[256, 32000] = h0[256,256] @ W_w[32000,256]^T + b_out
// bf16 mma.sync m16n8k16, fp32 accum.
// Block tile: M=256 (full batch) x N=128, K=256 fully resident in smem.
// 512 threads = 16 warps laid out 4(M) x 4(N); warp tile 64x32.
// Smem rows padded to 264 bf16 -> fragment LDS.32 are bank-conflict-free.
// ---------------------------------------------------------------------------
#define BN    128
#define APAD  264   // padded row stride (bf16 elements); 264*2=528B = 33*16B

__global__ void __launch_bounds__(512) logits_kernel(
    const float* __restrict__ W_w, const float* __restrict__ b_out,
    float* __restrict__ out)
{
    extern __shared__ __nv_bfloat16 smem[];
    __nv_bfloat16* A_s = smem;                    // [256][APAD] h0
    __nv_bfloat16* B_s = smem + B_SZ * APAD;      // [128][APAD] W_w slice

    const int tid = threadIdx.x;
    const int n0 = blockIdx.x * BN;

    // Load h0 (256x256 bf16 = 128KB) into A_s via uint4 (8 bf16) chunks
    {
        const uint4* src = (const uint4*)g_h0;
        for (int c = tid; c < (B_SZ * HID) / 8; c += 512) {
            int row  = c >> 5;        // 32 uint4 per row
            int col8 = c & 31;
            *(uint4*)(&A_s[row * APAD + col8 * 8]) = src[c];
        }
    }
    // Load W_w slice [128 rows x 256 fp32], convert to bf16 into B_s
    {
        for (int c = tid; c < BN * (HID / 4); c += 512) {
            int r  = c >> 6;          // 64 float4 per row
            int c4 = c & 63;
            float4 v = *(const float4*)(&W_w[(size_t)(n0 + r) * HID + c4 * 4]);
            __nv_bfloat162 p0 = __floats2bfloat162_rn(v.x, v.y);
            __nv_bfloat162 p1 = __floats2bfloat162_rn(v.z, v.w);
            *(__nv_bfloat162*)(&B_s[r * APAD + c4 * 4])     = p0;
            *(__nv_bfloat162*)(&B_s[r * APAD + c4 * 4 + 2]) = p1;
        }
    }
    __syncthreads();

    const int wid  = tid >> 5;
    const int lane = tid & 31;
    const int wm   = wid >> 2;      // 0..3 -> M offset wm*64
    const int wn   = wid & 3;       // 0..3 -> N offset wn*32
    const int gr   = lane >> 2;     // group (row within 8)
    const int tig  = lane & 3;      // thread-in-group

    float acc[4][4][4];
#pragma unroll
    for (int mi = 0; mi < 4; mi++)
#pragma unroll
        for (int ni = 0; ni < 4; ni++)
#pragma unroll
            for (int r = 0; r < 4; r++) acc[mi][ni][r] = 0.0f;

#pragma unroll
    for (int kk = 0; kk < HID / 16; kk++) {
        const int kb = kk * 16;
        uint32_t a[4][4];
#pragma unroll
        for (int mi = 0; mi < 4; mi++) {
            const __nv_bfloat16* p =
                &A_s[(wm * 64 + mi * 16 + gr) * APAD + kb + tig * 2];
            a[mi][0] = *(const uint32_t*)(p);
            a[mi][1] = *(const uint32_t*)(p + 8 * APAD);
            a[mi][2] = *(const uint32_t*)(p + 8);
            a[mi][3] = *(const uint32_t*)(p + 8 * APAD + 8);
        }
        uint32_t bf[4][2];
#pragma unroll
        for (int ni = 0; ni < 4; ni++) {
            const __nv_bfloat16* p =
                &B_s[(wn * 32 + ni * 8 + gr) * APAD + kb + tig * 2];
            bf[ni][0] = *(const uint32_t*)(p);
            bf[ni][1] = *(const uint32_t*)(p + 8);
        }
#pragma unroll
        for (int mi = 0; mi < 4; mi++) {
#pragma unroll
            for (int ni = 0; ni < 4; ni++) {
                asm volatile(
                    "mma.sync.aligned.m16n8k16.row.col.f32.bf16.bf16.f32 "
                    "{%0,%1,%2,%3}, {%4,%5,%6,%7}, {%8,%9}, {%0,%1,%2,%3};"
                    : "+f"(acc[mi][ni][0]), "+f"(acc[mi][ni][1]),
                      "+f"(acc[mi][ni][2]), "+f"(acc[mi][ni][3])
                    : "r"(a[mi][0]), "r"(a[mi][1]), "r"(a[mi][2]), "r"(a[mi][3]),
                      "r"(bf[ni][0]), "r"(bf[ni][1]));
            }
        }
    }

    // Epilogue: add b_out, write fp32 logits (float2 stores -> full 32B sectors)
    float bo0[4], bo1[4];
#pragma unroll
    for (int ni = 0; ni < 4; ni++) {
        int col = n0 + wn * 32 + ni * 8 + tig * 2;
        bo0[ni] = b_out[col];
        bo1[ni] = b_out[col + 1];
    }
#pragma unroll
    for (int mi = 0; mi < 4; mi++) {
        int row = wm * 64 + mi * 16 + gr;
#pragma unroll
        for (int ni = 0; ni < 4; ni++) {
            int col = n0 + wn * 32 + ni * 8 + tig * 2;
            float2 v0 = make_float2(acc[mi][ni][0] + bo0[ni],
                                    acc[mi][ni][1] + bo1[ni]);
            float2 v1 = make_float2(acc[mi][ni][2] + bo0[ni],
                                    acc[mi][ni][3] + bo1[ni]);
            *(float2*)(&out[(size_t)row * NCLS + col])       = v0;
            *(float2*)(&out[(size_t)(row + 8) * NCLS + col]) = v1;
        }
    }
}

// ---------------------------------------------------------------------------
// Launcher
// Input order (metadata.txt): 0=X 1=C_table 2=U_i 3=V_i 4=b_i 5=U_f 6=V_f 7=b_f
//  8=U_c 9=V_c 10=b_c 11=U_o 12=V_o 13=b_o 14..25=layer1 (unused) 26=W_w 27=b_out
// ---------------------------------------------------------------------------
extern "C" void kernel_launch(void* const* d_in, const int* in_sizes, int n_in,
                              void* d_out, int out_size)
{
    const int*   X       = (const int*)d_in[0];
    const float* C_table = (const float*)d_in[1];
    const float* U_i     = (const float*)d_in[2];
    const float* b_i     = (const float*)d_in[4];
    const float* U_c     = (const float*)d_in[8];
    const float* b_c     = (const float*)d_in[10];
    const float* U_o     = (const float*)d_in[11];
    const float* b_o     = (const float*)d_in[13];
    const float* W_w     = (const float*)d_in[26];
    const float* b_out   = (const float*)d_in[27];
    float* out = (float*)d_out;

    lstm_h0_kernel<<<B_SZ / 4, 256>>>(X, C_table, U_i, b_i, U_c, b_c, U_o, b_o);

    const int smem_bytes = (B_SZ * APAD + BN * APAD) * (int)sizeof(__nv_bfloat16);
    cudaFuncSetAttribute(logits_kernel,
                         cudaFuncAttributeMaxDynamicSharedMemorySize, smem_bytes);
    logits_kernel<<<NCLS / BN, 512, smem_bytes>>>(W_w, b_out, out);
}